// round 14
// baseline (speedup 1.0000x reference)
#include <cuda_runtime.h>
#include <cstdint>

// out[b,i,j] = x[b, i, i+j] if i+j < L else 0
// B=4, L=4096, LIMIT=256
#define MAXLEN 4096
#define LIMIT  256
#define BATCH  4

#define NROWS     (BATCH * MAXLEN)     // 16384
#define NBLOCKS   1024                 // single wave; 8192 warps
#define TPB       256                  // 8 warps
#define NWARPS    (NBLOCKS * (TPB/32)) // 8192 -> exactly 2 rows per warp
#define FULLM     0xFFFFFFFFu

// w1[lane] = src[lane+1], with src[32] supplied by nxt (same value all lanes)
__device__ __forceinline__ float4 shift_down1(float4 src, float4 nxt, int lane)
{
    float4 r;
    r.x = __shfl_down_sync(FULLM, src.x, 1);
    r.y = __shfl_down_sync(FULLM, src.y, 1);
    r.z = __shfl_down_sync(FULLM, src.z, 1);
    r.w = __shfl_down_sync(FULLM, src.w, 1);
    if (lane == 31) r = nxt;
    return r;
}

struct RowCtx {
    const float4* xr;
    float4* orow;
    int a, lim;
    float4 A, B, C;
};

__device__ __forceinline__ void row_setup(RowCtx& c,
                                          const float* __restrict__ x,
                                          float* __restrict__ out,
                                          int row, int lane)
{
    const int i   = row & (MAXLEN - 1);
    const int bc4 = i >> 2;
    c.a   = i & 3;
    c.lim = MAXLEN - i;
    c.xr  = reinterpret_cast<const float4*>(x) + ((size_t)row << 10);
    c.orow= reinterpret_cast<float4*>(out) + ((size_t)row << 6);
    // Each 16B block loaded exactly ONCE, L2-only (no reuse -> skip L1).
    c.A = __ldcg(c.xr + min(bc4 + lane,      1023));
    c.B = __ldcg(c.xr + min(bc4 + 32 + lane, 1023));
    c.C = __ldcg(c.xr + min(bc4 + 64,        1023));
}

__device__ __forceinline__ void row_emit(const RowCtx& c, int lane)
{
    const float4 B0x = { __shfl_sync(FULLM, c.B.x, 0), __shfl_sync(FULLM, c.B.y, 0),
                         __shfl_sync(FULLM, c.B.z, 0), __shfl_sync(FULLM, c.B.w, 0) };
    const int a = c.a;

    #pragma unroll
    for (int it = 0; it < 2; it++) {
        const int o = lane + it * 32;        // output f4 index (0..63)
        const float4 w0 = it ? c.B : c.A;
        const float4 w1 = it ? shift_down1(c.B, c.C, lane)
                             : shift_down1(c.A, B0x, lane);

        float4 v;                            // funnel shift by a floats
        if      (a == 0) { v.x = w0.x; v.y = w0.y; v.z = w0.z; v.w = w0.w; }
        else if (a == 1) { v.x = w0.y; v.y = w0.z; v.z = w0.w; v.w = w1.x; }
        else if (a == 2) { v.x = w0.z; v.y = w0.w; v.z = w1.x; v.w = w1.y; }
        else             { v.x = w0.w; v.y = w1.x; v.z = w1.y; v.w = w1.z; }

        const int j0 = o << 2;
        if (j0 + 3 >= c.lim) {               // rare tail rows only
            if (j0 + 0 >= c.lim) v.x = 0.0f;
            if (j0 + 1 >= c.lim) v.y = 0.0f;
            if (j0 + 2 >= c.lim) v.z = 0.0f;
            if (j0 + 3 >= c.lim) v.w = 0.0f;
        }
        c.orow[o] = v;
    }
}

__global__ __launch_bounds__(TPB)
void band_gather_kernel(const float* __restrict__ x, float* __restrict__ out)
{
    const int lane = threadIdx.x & 31;
    const int warp = blockIdx.x * (TPB / 32) + (threadIdx.x >> 5);

    // Exactly 2 rows per warp, perfectly balanced. Batch both rows' loads
    // (6 LDGs in flight) before either row's stores.
    RowCtx c0, c1;
    row_setup(c0, x, out, warp,          lane);
    row_setup(c1, x, out, warp + NWARPS, lane);
    row_emit(c0, lane);
    row_emit(c1, lane);
}

extern "C" void kernel_launch(void* const* d_in, const int* in_sizes, int n_in,
                              void* d_out, int out_size)
{
    (void)in_sizes; (void)n_in; (void)out_size;
    const float* x = (const float*)d_in[0];
    float* out = (float*)d_out;
    band_gather_kernel<<<NBLOCKS, TPB>>>(x, out);
}